// round 5
// baseline (speedup 1.0000x reference)
#include <cuda_runtime.h>

#define Nn      1000
#define INF_    32
#define Hh      128
#define Mm      128
#define DEGc    16
#define Pp      2
#define OUTn    10
#define NSTART  64
#define MAXM    10000
#define QCAP    10016
#define MSGCAP  640
#define THRv    (1.0f - 1e-7f)

typedef unsigned long long ull;
typedef unsigned short u16;

__device__ float g_feats[Nn*Hh];
__device__ float g_msgs[MSGCAP*Mm];

__device__ __forceinline__ ull pack2(float a, float b){
    ull r; asm("mov.b64 %0, {%1,%2};" : "=l"(r) : "f"(a), "f"(b)); return r;
}
__device__ __forceinline__ ull fma2(ull a, ull b, ull c){
    ull d; asm("fma.rn.f32x2 %0, %1, %2, %3;" : "=l"(d) : "l"(a), "l"(b), "l"(c)); return d;
}

__global__ void enc_kernel(const float* __restrict__ xa,
                           const float* __restrict__ ew,
                           const float* __restrict__ eb)
{
    __shared__ float sx[INF_];
    int nrow = blockIdx.x;
    if (threadIdx.x < INF_) sx[threadIdx.x] = xa[nrow*INF_ + threadIdx.x];
    __syncthreads();
    int h = threadIdx.x;
    float a = eb[h];
    #pragma unroll
    for (int i = 0; i < INF_; i++) a = fmaf(sx[i], ew[i*Hh + h], a);
    g_feats[nrow*Hh + h] = a;
}

// ---- shared layout (float units) ----
#define OFF_NSW  0                     // 32768 (256x128 as ull[256][64])
#define OFF_RNS  (OFF_NSW + 256*Hh)    // 2048  (16 rows x 64 ull)
#define OFF_RNM  (OFF_RNS + 2048)      // 2048
#define OFF_X2   (OFF_RNM + 2048)      // 256   (128 ull splatted ns)
#define OFF_AW   (OFF_X2  + 256)       // 256
#define OFF_NSB  (OFF_AW  + 256)       // 128
#define OFF_NMB  (OFF_NSB + 128)       // 128
#define OFF_G    (OFF_NMB + 128)       // 128
#define OFF_ACTP (OFF_G   + 128)       // 16
#define OFF_TACT (OFF_ACTP+ 16)        // 1000
#define OFF_QN   (OFF_TACT+ Nn)        // 5008 floats = 10016 u16
#define OFF_NB   (OFF_QN  + 5008)      // 16 ints
#define OFF_CI   (OFF_NB  + 16)        // 12 ints: head,tail,pc,node,e,done,same,msgsame,key
#define OFF_CF   (OFF_CI  + 12)        // 2 floats: act_b, new_act
#define SMEM_FLOATS (OFF_CF + 4)
#define SMEM_BYTES  (SMEM_FLOATS*4)

__device__ __forceinline__ void scan_q(int l, int curnode,
    const u16* s_qn, const float* s_tact, int* s_ci)
{
    int head = s_ci[0], tail = s_ci[1];
    int lim = tail < MAXM ? tail : MAXM;
    bool found = false;
    while (head < lim) {
        int idx = head + l;
        bool v = idx < lim;
        int nodel = v ? (int)s_qn[idx] : 0;
        float ta = v ? s_tact[nodel] : 2.0f;
        unsigned bal = __ballot_sync(0xffffffffu, v && (ta <= THRv));
        if (bal) {
            int f = __ffs(bal) - 1;
            if (l == f) {
                s_ci[3] = nodel; s_ci[4] = idx;
                s_ci[6] = (nodel == curnode) ? 1 : 0;
                int key = (idx < NSTART) ? idx : (NSTART + ((idx - NSTART) >> 4));
                s_ci[7] = (key == s_ci[8]) ? 1 : 0;
                s_ci[8] = key;
            }
            if (l == 0) s_ci[0] = head + f + 1;
            found = true; break;
        }
        head += 32;
    }
    if (!found && l == 0) s_ci[5] = 1;
}

__global__ void __launch_bounds__(1024, 1) serial_kernel(
    const float* __restrict__ fm,  const int*   __restrict__ nbr,
    const float* __restrict__ nsw, const float* __restrict__ nsb,
    const float* __restrict__ nmw, const float* __restrict__ nmb,
    const float* __restrict__ aw,  const float* __restrict__ ab,
    const float* __restrict__ dw,  const float* __restrict__ db,
    float* __restrict__ out)
{
    extern __shared__ float sm[];
    ull*   s_nsw2 = (ull*)(sm + OFF_NSW);
    float* s_rns  = sm + OFF_RNS;  ull* s_rns2 = (ull*)s_rns;
    float* s_rnm  = sm + OFF_RNM;  ull* s_rnm2 = (ull*)s_rnm;
    ull*   s_x2u  = (ull*)(sm + OFF_X2);
    float* s_aw   = sm + OFF_AW;
    float* s_nsb  = sm + OFF_NSB;
    float* s_nmb  = sm + OFF_NMB;
    float* s_g    = sm + OFF_G;
    float* s_actp = sm + OFF_ACTP;
    float* s_tact = sm + OFF_TACT;
    u16*   s_qn   = (u16*)(sm + OFF_QN);
    int*   s_nb   = (int*)(sm + OFF_NB);
    int*   s_ci   = (int*)(sm + OFF_CI);
    float* s_cf   = sm + OFF_CF;

    const int t  = threadIdx.x;
    const int w  = t >> 5, l = t & 31;
    const int j2 = ((w & 1) << 5) | l;     // pair-column 0..63
    const int rr = w >> 1;                 // k-chunk 0..15 (16 inputs each)
    const int i16 = l & 15;

    // ---- init ----
    for (int i = t; i < (256*Hh)/4; i += 1024)
        ((float4*)(sm + OFF_NSW))[i] = ((const float4*)nsw)[i];
    if (t < 256) s_aw[t] = aw[t];
    if (t < 128) { s_nsb[t] = nsb[t]; s_nmb[t] = nmb[t]; s_g[t] = 0.f; }
    if (t < Nn)  s_tact[t] = 0.f;
    if (t < NSTART) s_qn[t] = (u16)t;
    if (t == 0) {
        s_ci[0] = 0; s_ci[1] = NSTART; s_ci[2] = 0; s_ci[5] = 0; s_ci[8] = -1;
        s_cf[0] = ab[0];
    }
    // nm_w rows [16rr,16rr+16) in registers as f32x2
    ull wnm[16];
    #pragma unroll
    for (int i = 0; i < 16; i++) {
        const float2 v = *(const float2*)(nmw + (16*rr + i)*Hh + 2*j2);
        wnm[i] = pack2(v.x, v.y);
    }
    __syncthreads();
    if (w == 0) scan_q(l, -1, s_qn, s_tact, s_ci);
    __syncthreads();

    while (!s_ci[5]) {
        const int node = s_ci[3], e = s_ci[4], pc = s_ci[2], tail = s_ci[1];
        const int same = s_ci[6], msgsame = s_ci[7];

        // ---- ph1: NS partials (+ msg recompute on key change) + act + nbr ----
        if (rr < 8) {
            const int k = 16*rr + i16;
            float xg = 0.f;
            if (l < 16) xg = same ? sm[OFF_X2 + 2*k] : g_feats[node*Hh + k];
            ull acc = 0ull;
            const ull* wb = s_nsw2 + (size_t)(16*rr)*64 + j2;
            #pragma unroll
            for (int kk = 0; kk < 16; kk++) {
                float xk = __shfl_sync(0xffffffffu, xg, kk);
                acc = fma2(pack2(xk, xk), wb[kk*64], acc);
            }
            s_rns2[rr*64 + j2] = acc;
            float ap = (l < 16) ? xg * s_aw[k] : 0.f;
            #pragma unroll
            for (int o = 16; o; o >>= 1) ap += __shfl_xor_sync(0xffffffffu, ap, o);
            if (l == 0) s_actp[rr] = ap;
        } else {
            if (!msgsame) {
                const int kp = 16*(rr - 8) + i16;          // msg element
                float xg = 0.f;
                if (l < 16) {
                    const float* mp = (e < NSTART) ? (fm + e*Mm)
                                                   : (g_msgs + ((e - NSTART) >> 4)*Mm);
                    xg = mp[kp];
                }
                ull acc = 0ull, acc2 = 0ull;
                const ull* wb = s_nsw2 + (size_t)(Hh + 16*(rr - 8))*64 + j2;
                #pragma unroll
                for (int kk = 0; kk < 16; kk++) {
                    float xk = __shfl_sync(0xffffffffu, xg, kk);
                    ull xs = pack2(xk, xk);
                    acc  = fma2(xs, wb[kk*64], acc);
                    acc2 = fma2(xs, wnm[kk], acc2);
                }
                s_rns2[rr*64 + j2] = acc;
                s_rnm2[rr*64 + j2] = acc2;
                float ap = (l < 16) ? xg * s_aw[Hh + kp] : 0.f;
                #pragma unroll
                for (int o = 16; o; o >>= 1) ap += __shfl_xor_sync(0xffffffffu, ap, o);
                if (l == 0) s_actp[rr] = ap;
            }
            if (w == 31 && l < DEGc) s_nb[l] = nbr[node*DEGc + l];
        }
        __syncthreads();

        // ---- ph2: ns reduce -> relu -> splat ; act finalize ; enqueue ----
        if (t < 128) {
            float v = s_nsb[t];
            #pragma unroll
            for (int q = 0; q < 16; q++) v += s_rns[q*128 + t];
            v = fmaxf(v, 0.f);
            s_x2u[t] = pack2(v, v);
        } else if (t == 128) {
            float z = s_cf[0];
            #pragma unroll
            for (int q = 0; q < 16; q++) z += s_actp[q];
            float cand = 1.f / (1.f + expf(-z));
            float ta = s_tact[node];
            float na = (ta + cand > 1.0f) ? (1.0f - ta) : cand;
            s_cf[1] = na;
            s_tact[node] = ta + na;
        } else if (w == 5 && l < DEGc) {
            int idx = tail + l;
            if (idx < QCAP) s_qn[idx] = (u16)s_nb[l];
        } else if (t == 192) {
            s_ci[1] = tail + DEGc;
            s_ci[2] = pc + 1;
        }
        __syncthreads();

        // ---- ph3: NM ns-half partials ; scan (warp 16) ----
        if (rr < 8) {
            ull acc = 0ull;
            const ull* xs = s_x2u + 16*rr;
            #pragma unroll
            for (int kk = 0; kk < 16; kk++)
                acc = fma2(xs[kk], wnm[kk], acc);          // uniform LDS.64 broadcast
            s_rnm2[rr*64 + j2] = acc;
        } else if (w == 16) {
            scan_q(l, node, s_qn, s_tact, s_ci);
        }
        __syncthreads();

        // ---- ph4: commit message / feats / readout ----
        if (t < 128) {
            if (pc < MSGCAP) {
                float v = s_nmb[t];
                #pragma unroll
                for (int q = 0; q < 16; q++) v += s_rnm[q*128 + t];
                g_msgs[pc*Mm + t] = v;
            }
        } else if (t < 256) {
            int idx = t - 128;
            float nsv = sm[OFF_X2 + 2*idx];
            g_feats[node*Hh + idx] = nsv;
            s_g[idx] += nsv * s_cf[1];
        }
        __syncthreads();
    }

    // ---- decode + log_softmax ----
    if (t < Pp*OUTn) {
        int p = t / OUTn, o = t % OUTn;
        float z = db[p*OUTn + o];
        #pragma unroll 8
        for (int h = 0; h < Hh; h++) z = fmaf(s_g[h], dw[(p*Hh + h)*OUTn + o], z);
        s_rns[t] = z;
    }
    __syncthreads();
    if (t < Pp) {
        float mx = -1e30f;
        for (int o = 0; o < OUTn; o++) mx = fmaxf(mx, s_rns[t*OUTn + o]);
        float se = 0.f;
        for (int o = 0; o < OUTn; o++) se += expf(s_rns[t*OUTn + o] - mx);
        float ls = logf(se);
        for (int o = 0; o < OUTn; o++) out[t*OUTn + o] = s_rns[t*OUTn + o] - mx - ls;
    }
}

extern "C" void kernel_launch(void* const* d_in, const int* in_sizes, int n_in,
                              void* d_out, int out_size)
{
    const float* xa  = (const float*)d_in[0];
    const float* fm  = (const float*)d_in[1];
    const int*   nbv = (const int*)  d_in[2];
    const float* ew  = (const float*)d_in[4];
    const float* eb  = (const float*)d_in[5];
    const float* nsw = (const float*)d_in[6];
    const float* nsb = (const float*)d_in[7];
    const float* nmw = (const float*)d_in[8];
    const float* nmb = (const float*)d_in[9];
    const float* aw  = (const float*)d_in[10];
    const float* ab  = (const float*)d_in[11];
    const float* dw  = (const float*)d_in[12];
    const float* db  = (const float*)d_in[13];
    float* out = (float*)d_out;

    cudaFuncSetAttribute(serial_kernel,
                         cudaFuncAttributeMaxDynamicSharedMemorySize, SMEM_BYTES);

    enc_kernel<<<Nn, Hh>>>(xa, ew, eb);
    serial_kernel<<<1, 1024, SMEM_BYTES>>>(fm, nbv, nsw, nsb, nmw, nmb,
                                           aw, ab, dw, db, out);
}